// round 14
// baseline (speedup 1.0000x reference)
#include <cuda_runtime.h>
#include <stdint.h>

// ---------------- problem constants ----------------
// SPARSE_SHAPE (468,468,1), WINDOW (12,12,1), BATCH 4
// _NX=_NY=40, _NZ=2 ; win_z==0 always ; full_win = 2*compact
// compact win id = b*1600 + wx*40 + wy  in [0, 6400)
#define NWc   6400
#define CAP   512               // max voxels per window (uniform data: ~49 mean)
#define MAXN  327680
#define FULLM 0xFFFFFFFFu
#define KLOG  0.4152410118609203f   // 4*log2(1e4)/128

// ---------------- static scratch (no allocations allowed) -------------------
__device__ int           g_cnt0[NWc];
__device__ int           g_cnt1[NWc];
__device__ int           g_bkt0[NWc * CAP];
__device__ int           g_bkt1[NWc * CAP];
__device__ int           g_winc0[MAXN];
__device__ int           g_winc1[MAXN];
__device__ int           g_inner0[MAXN];
__device__ int           g_inner1[MAXN];
__device__ unsigned char g_keep0[MAXN];
__device__ unsigned char g_keepF[MAXN];

__device__ __forceinline__ void lvl_target(int n, int& lvl, int& target) {
    if (n < 16)      { lvl = 0; target = 16; }
    else if (n < 32) { lvl = 1; target = 32; }
    else if (n < 64) { lvl = 2; target = 64; }
    else             { lvl = 3; target = 144; }
}

// ---------------- phase 0: zero the 2x6400 window counters ------------------
__global__ void k_zerocnt() {
    int i = blockIdx.x * blockDim.x + threadIdx.x;
    if (i < NWc) { g_cnt0[i] = 0; g_cnt1[i] = 0; }
}

// ---------------- phase 1: window ids + bucket scatter (round 0) ------------
__global__ void k_scatter0(const int* __restrict__ coords, int N) {
    int i = blockIdx.x * blockDim.x + threadIdx.x;
    if (i < N) {
        int4 cc = ((const int4*)coords)[i];          // (b,z,y,x)
        int b = cc.x, y = cc.z, x = cc.w;
        int w0 = b * 1600 + ((x + 12) / 12) * 40 + ((y + 12) / 12);
        int w1 = b * 1600 + ((x + 6)  / 12) * 40 + ((y + 6)  / 12);
        g_winc0[i] = w0;
        g_winc1[i] = w1;
        int pos = atomicAdd(&g_cnt0[w0], 1);
        if (pos < CAP) g_bkt0[w0 * CAP + pos] = i;
    }
}

// ---------------- phase 2: rank round 0 + inline scatter to round-1 buckets -
// rank of element = number of bucket entries with smaller voxel index (stable).
__global__ void __launch_bounds__(64)
k_wrank0s1() {
    __shared__ int s[CAP];
    int w = blockIdx.x;
    int n = g_cnt0[w];
    if (n > CAP) n = CAP;
    for (int t = threadIdx.x; t < n; t += 64) s[t] = g_bkt0[w * CAP + t];
    __syncthreads();
    int lvl, target; lvl_target(n, lvl, target);
    for (int e = threadIdx.x; e < n; e += 64) {
        int my = s[e];
        int r = 0;
        for (int j = 0; j < n; j++) r += (s[j] < my);
        g_inner0[my] = r;
        int kp = (r < target);
        g_keep0[my] = kp;
        if (kp) {
            int w1 = g_winc1[my];
            int pos = atomicAdd(&g_cnt1[w1], 1);
            if (pos < CAP) g_bkt1[w1 * CAP + pos] = my;
        } else {
            g_inner1[my] = -1;
            g_keepF[my]  = 0;
        }
    }
}

// ---------------- phase 3: per-window stable rank (round 1) -----------------
__global__ void __launch_bounds__(64)
k_wrank1() {
    __shared__ int s[CAP];
    int w = blockIdx.x;
    int n = g_cnt1[w];
    if (n > CAP) n = CAP;
    for (int t = threadIdx.x; t < n; t += 64) s[t] = g_bkt1[w * CAP + t];
    __syncthreads();
    int lvl, target; lvl_target(n, lvl, target);
    for (int e = threadIdx.x; e < n; e += 64) {
        int my = s[e];
        int r = 0;
        for (int j = 0; j < n; j++) r += (s[j] < my);
        g_inner1[my] = r;
        g_keepF[my]  = (r < target) ? 1 : 0;
    }
}

// ---------------- phase 4: scalar output vectors (flat, non-divergent) ------
__global__ void k_outvec(float* __restrict__ out, int N,
                         size_t off_keep, size_t off_w0, size_t off_w1,
                         size_t off_dl0, size_t off_dl1,
                         size_t off_i0, size_t off_i1) {
    for (int i = blockIdx.x * blockDim.x + threadIdx.x; i < N;
         i += gridDim.x * blockDim.x) {
        int w0 = g_winc0[i], w1 = g_winc1[i];
        out[off_keep + i] = g_keepF[i] ? 1.0f : 0.0f;
        out[off_w0 + i]   = (float)(2 * w0);
        out[off_w1 + i]   = (float)(2 * w1);
        int l0, t0; lvl_target(g_cnt0[w0], l0, t0);
        out[off_dl0 + i] = (float)l0;
        float dl1 = -1.0f;
        if (g_keep0[i]) {
            int l1, t1; lvl_target(g_cnt1[w1], l1, t1);
            dl1 = (float)l1;
        }
        out[off_dl1 + i] = dl1;
        out[off_i0 + i] = (float)g_inner0[i];
        out[off_i1 + i] = (float)g_inner1[i];
    }
}

// ---------------- main BW kernel: UNMASKED feat copy + pe0 + pe1 ------------
// Starts at t=0 (no dependency on the rank chain). One block = 4 rows, warp
// per row, all traffic 128-bit. The keep mask is applied afterwards by
// k_fixup, which zeroes exactly the dropped rows.
__global__ void __launch_bounds__(128)
k_main(const float* __restrict__ feat, const int* __restrict__ coords,
       float* __restrict__ out, int N, size_t off_pe0, size_t off_pe1) {
    int warp = threadIdx.x >> 5, lane = threadIdx.x & 31;
    int i = blockIdx.x * 4 + warp;
    if (i >= N) return;
    int t = lane & 15;
    float rec0 = exp2f(-(float)(2 * t)     * KLOG);
    float rec1 = exp2f(-(float)(2 * t + 1) * KLOG);

    int x = __ldg(&coords[i * 4 + 3]);
    int y = __ldg(&coords[i * 4 + 2]);
    int v = (lane < 16) ? x : y;
    float v0 = (float)(v % 12) - 6.0f;
    float v1 = (float)((v + 6) % 12) - 6.0f;

    size_t row4 = (size_t)i * 32 + lane;
    ((float4*)out)[row4] = ((const float4*)feat)[row4];   // unmasked copy

    float4 p0, p1; float a;
    a = v0 * rec0; p0.x = __sinf(a); p0.y = __cosf(a);
    a = v0 * rec1; p0.z = __sinf(a); p0.w = __cosf(a);
    a = v1 * rec0; p1.x = __sinf(a); p1.y = __cosf(a);
    a = v1 * rec1; p1.z = __sinf(a); p1.w = __cosf(a);
    ((float4*)(out + off_pe0))[row4] = p0;
    ((float4*)(out + off_pe1))[row4] = p1;
}

// ---------------- fixup: zero the feat rows that were dropped ---------------
// Runs after BOTH k_main and the rank chain. Expected dropped rows ~0
// (windows rarely exceed their token target), so this is ~a keepF scan.
__global__ void __launch_bounds__(128)
k_fixup(float* __restrict__ out, int N) {
    int warp = threadIdx.x >> 5, lane = threadIdx.x & 31;
    const float4 z4 = make_float4(0.f, 0.f, 0.f, 0.f);
    for (int i = blockIdx.x * 4 + warp; i < N; i += gridDim.x * 4) {
        unsigned char kp = g_keepF[i];
        if (!kp) {
            ((float4*)out)[(size_t)i * 32 + lane] = z4;
        }
    }
}

// ---------------- launch ----------------
extern "C" void kernel_launch(void* const* d_in, const int* in_sizes, int n_in,
                              void* d_out, int out_size) {
    const float* feat   = (const float*)d_in[0];
    const int*   coords = (const int*)d_in[1];
    int N = in_sizes[1] / 4;
    int C = in_sizes[0] / N;          // 128 (layout constants assume this)
    if (N > MAXN) N = MAXN;

    float* out = (float*)d_out;
    size_t Ns = (size_t)N, Cs = (size_t)C;
    size_t off = Ns * Cs;             // feat at 0
    size_t off_keep = off; off += Ns;
    size_t off_w0   = off; off += Ns;
    size_t off_w1   = off; off += Ns;
    size_t off_dl0  = off; off += Ns;
    size_t off_dl1  = off; off += Ns;
    size_t off_i0   = off; off += Ns;
    size_t off_i1   = off; off += Ns;
    size_t off_pe0  = off; off += Ns * Cs;
    size_t off_pe1  = off;

    // Fork: aux chain on HIGH-priority s2; the big BW kernel (short blocks)
    // on the captured stream. Join, then fixup applies the keep mask.
    int prLow = 0, prHigh = 0;
    cudaDeviceGetStreamPriorityRange(&prLow, &prHigh);
    cudaStream_t s2;
    cudaStreamCreateWithPriority(&s2, cudaStreamNonBlocking, prHigh);
    cudaEvent_t eFork, eJoin;
    cudaEventCreateWithFlags(&eFork, cudaEventDisableTiming);
    cudaEventCreateWithFlags(&eJoin, cudaEventDisableTiming);

    cudaEventRecord(eFork, 0);
    cudaStreamWaitEvent(s2, eFork, 0);

    // branch A (s2, high prio): rank chain + scalar outputs (~10 MB total)
    k_zerocnt<<<(NWc + 255) / 256, 256, 0, s2>>>();
    k_scatter0<<<(N + 255) / 256, 256, 0, s2>>>(coords, N);
    k_wrank0s1<<<NWc, 64, 0, s2>>>();
    k_wrank1<<<NWc, 64, 0, s2>>>();
    k_outvec<<<592, 256, 0, s2>>>(out, N, off_keep, off_w0, off_w1,
                                  off_dl0, off_dl1, off_i0, off_i1);

    // branch B (captured stream): ALL bulk traffic from t=0 (623 MB)
    k_main<<<(N + 3) / 4, 128>>>(feat, coords, out, N, off_pe0, off_pe1);

    cudaEventRecord(eJoin, s2);
    cudaStreamWaitEvent(0, eJoin, 0);   // join: keepF ready, k_main ordered on 0

    // apply keep mask to the (few) dropped rows
    k_fixup<<<1184, 128>>>(out, N);
    // s2/events deliberately not destroyed: destroying capture-participating
    // resources invalidates the graph; kernel_launch runs only a few times.
}

// round 15
// speedup vs baseline: 1.1117x; 1.1117x over previous
#include <cuda_runtime.h>
#include <stdint.h>

// ---------------- problem constants ----------------
// SPARSE_SHAPE (468,468,1), WINDOW (12,12,1), BATCH 4
// _NX=_NY=40, _NZ=2 ; win_z==0 always ; full_win = 2*compact
// compact win id = b*1600 + wx*40 + wy  in [0, 6400)
#define NWc   6400
#define CAP   512               // max voxels per window (uniform data: ~49 mean)
#define MAXN  327680
#define FULLM 0xFFFFFFFFu
#define KLOG  0.4152410118609203f   // 4*log2(1e4)/128

// ---------------- static scratch (no allocations allowed) -------------------
__device__ int           g_cnt0[NWc];
__device__ int           g_cnt1[NWc];
__device__ int           g_bkt0[NWc * CAP];
__device__ int           g_bkt1[NWc * CAP];
__device__ int           g_winc0[MAXN];
__device__ int           g_winc1[MAXN];
__device__ int           g_inner0[MAXN];
__device__ int           g_inner1[MAXN];
__device__ unsigned char g_keep0[MAXN];
__device__ unsigned char g_keepF[MAXN];

__device__ __forceinline__ void lvl_target(int n, int& lvl, int& target) {
    if (n < 16)      { lvl = 0; target = 16; }
    else if (n < 32) { lvl = 1; target = 32; }
    else if (n < 64) { lvl = 2; target = 64; }
    else             { lvl = 3; target = 144; }
}

// ---------------- phase 0: zero the 2x6400 window counters ------------------
__global__ void k_zerocnt() {
    int i = blockIdx.x * blockDim.x + threadIdx.x;
    if (i < NWc) { g_cnt0[i] = 0; g_cnt1[i] = 0; }
}

// ---------------- phase 1: window ids + bucket scatter (round 0) ------------
__global__ void k_scatter0(const int* __restrict__ coords, int N) {
    int i = blockIdx.x * blockDim.x + threadIdx.x;
    if (i < N) {
        int4 cc = ((const int4*)coords)[i];          // (b,z,y,x)
        int b = cc.x, y = cc.z, x = cc.w;
        int w0 = b * 1600 + ((x + 12) / 12) * 40 + ((y + 12) / 12);
        int w1 = b * 1600 + ((x + 6)  / 12) * 40 + ((y + 6)  / 12);
        g_winc0[i] = w0;
        g_winc1[i] = w1;
        int pos = atomicAdd(&g_cnt0[w0], 1);
        if (pos < CAP) g_bkt0[w0 * CAP + pos] = i;
    }
}

// ---------------- phase 2: rank round 0 + inline scatter to round-1 buckets -
__global__ void __launch_bounds__(64)
k_wrank0s1() {
    __shared__ int s[CAP];
    int w = blockIdx.x;
    int n = g_cnt0[w];
    if (n > CAP) n = CAP;
    for (int t = threadIdx.x; t < n; t += 64) s[t] = g_bkt0[w * CAP + t];
    __syncthreads();
    int lvl, target; lvl_target(n, lvl, target);
    for (int e = threadIdx.x; e < n; e += 64) {
        int my = s[e];
        int r = 0;
        for (int j = 0; j < n; j++) r += (s[j] < my);
        g_inner0[my] = r;
        int kp = (r < target);
        g_keep0[my] = kp;
        if (kp) {
            int w1 = g_winc1[my];
            int pos = atomicAdd(&g_cnt1[w1], 1);
            if (pos < CAP) g_bkt1[w1 * CAP + pos] = my;
        } else {
            g_inner1[my] = -1;
            g_keepF[my]  = 0;
        }
    }
}

// ---------------- phase 3: per-window stable rank (round 1) -----------------
__global__ void __launch_bounds__(64)
k_wrank1() {
    __shared__ int s[CAP];
    int w = blockIdx.x;
    int n = g_cnt1[w];
    if (n > CAP) n = CAP;
    for (int t = threadIdx.x; t < n; t += 64) s[t] = g_bkt1[w * CAP + t];
    __syncthreads();
    int lvl, target; lvl_target(n, lvl, target);
    for (int e = threadIdx.x; e < n; e += 64) {
        int my = s[e];
        int r = 0;
        for (int j = 0; j < n; j++) r += (s[j] < my);
        g_inner1[my] = r;
        g_keepF[my]  = (r < target) ? 1 : 0;
    }
}

// ---------------- branch B: positional embeddings, SHORT blocks -------------
// One block = exactly 4 rows (warp per row), then exit. Short blocks recycle
// SM slots constantly so the concurrent aux chain co-schedules immediately.
__global__ void __launch_bounds__(128)
k_pe4(const int* __restrict__ coords, float* __restrict__ out, int N,
      size_t off_pe0, size_t off_pe1) {
    int warp = threadIdx.x >> 5, lane = threadIdx.x & 31;
    int i = blockIdx.x * 4 + warp;
    if (i >= N) return;
    int t = lane & 15;
    float rec0 = exp2f(-(float)(2 * t)     * KLOG);
    float rec1 = exp2f(-(float)(2 * t + 1) * KLOG);

    int x = __ldg(&coords[i * 4 + 3]);
    int y = __ldg(&coords[i * 4 + 2]);
    int v = (lane < 16) ? x : y;
    float v0 = (float)(v % 12) - 6.0f;
    float v1 = (float)((v + 6) % 12) - 6.0f;

    float4 p0, p1; float a;
    a = v0 * rec0; p0.x = __sinf(a); p0.y = __cosf(a);
    a = v0 * rec1; p0.z = __sinf(a); p0.w = __cosf(a);
    a = v1 * rec0; p1.x = __sinf(a); p1.y = __cosf(a);
    a = v1 * rec1; p1.z = __sinf(a); p1.w = __cosf(a);

    size_t row4 = (size_t)i * 32 + lane;
    ((float4*)(out + off_pe0))[row4] = p0;
    ((float4*)(out + off_pe1))[row4] = p1;
}

// ---------------- final: feat mask + scalar vectors over row range [lo,hi) --
// Blocks [0,Gv): warp-per-row float4 feat masking (grid-stride).
// Blocks [Gv,..): flat one-thread-per-voxel scalar outputs.
// Block-granular split: control flow uniform inside each block.
__global__ void __launch_bounds__(128)
k_featvec(const float* __restrict__ feat, float* __restrict__ out,
          int lo, int hi, int Gv,
          size_t off_keep, size_t off_w0, size_t off_w1,
          size_t off_dl0, size_t off_dl1, size_t off_i0, size_t off_i1) {
    if (blockIdx.x < (unsigned)Gv) {
        int warp = threadIdx.x >> 5, lane = threadIdx.x & 31;
        for (int i = lo + blockIdx.x * 4 + warp; i < hi; i += Gv * 4) {
            float kf = g_keepF[i] ? 1.0f : 0.0f;
            size_t row4 = (size_t)i * 32 + lane;
            float4 f = ((const float4*)feat)[row4];
            f.x *= kf; f.y *= kf; f.z *= kf; f.w *= kf;
            ((float4*)out)[row4] = f;
        }
    } else {
        int nb = gridDim.x - Gv;
        for (int i = lo + (blockIdx.x - Gv) * 128 + threadIdx.x; i < hi;
             i += nb * 128) {
            int w0 = g_winc0[i], w1 = g_winc1[i];
            out[off_keep + i] = g_keepF[i] ? 1.0f : 0.0f;
            out[off_w0 + i]   = (float)(2 * w0);
            out[off_w1 + i]   = (float)(2 * w1);
            int l0, t0; lvl_target(g_cnt0[w0], l0, t0);
            out[off_dl0 + i] = (float)l0;
            float dl1 = -1.0f;
            if (g_keep0[i]) {
                int l1, t1; lvl_target(g_cnt1[w1], l1, t1);
                dl1 = (float)l1;
            }
            out[off_dl1 + i] = dl1;
            out[off_i0 + i] = (float)g_inner0[i];
            out[off_i1 + i] = (float)g_inner1[i];
        }
    }
}

// ---------------- launch ----------------
extern "C" void kernel_launch(void* const* d_in, const int* in_sizes, int n_in,
                              void* d_out, int out_size) {
    const float* feat   = (const float*)d_in[0];
    const int*   coords = (const int*)d_in[1];
    int N = in_sizes[1] / 4;
    int C = in_sizes[0] / N;          // 128 (layout constants assume this)
    if (N > MAXN) N = MAXN;

    float* out = (float*)d_out;
    size_t Ns = (size_t)N, Cs = (size_t)C;
    size_t off = Ns * Cs;             // feat at 0
    size_t off_keep = off; off += Ns;
    size_t off_w0   = off; off += Ns;
    size_t off_w1   = off; off += Ns;
    size_t off_dl0  = off; off += Ns;
    size_t off_dl1  = off; off += Ns;
    size_t off_i0   = off; off += Ns;
    size_t off_i1   = off; off += Ns;
    size_t off_pe0  = off; off += Ns * Cs;
    size_t off_pe1  = off;

    int prLow = 0, prHigh = 0;
    cudaDeviceGetStreamPriorityRange(&prLow, &prHigh);
    cudaStream_t s2;
    cudaStreamCreateWithPriority(&s2, cudaStreamNonBlocking, prHigh);
    cudaEvent_t eFork, eMid, eJoin;
    cudaEventCreateWithFlags(&eFork, cudaEventDisableTiming);
    cudaEventCreateWithFlags(&eMid,  cudaEventDisableTiming);
    cudaEventCreateWithFlags(&eJoin, cudaEventDisableTiming);

    cudaEventRecord(eFork, 0);
    cudaStreamWaitEvent(s2, eFork, 0);

    int Nh = ((N / 2) + 3) & ~3;      // row-range split point (multiple of 4)
    int Gv = 592, Gs = 296;           // vector / scalar blocks per half

    // branch A (s2, high prio): rank chain, then first half of feat+scalars
    k_zerocnt<<<(NWc + 255) / 256, 256, 0, s2>>>();
    k_scatter0<<<(N + 255) / 256, 256, 0, s2>>>(coords, N);
    k_wrank0s1<<<NWc, 64, 0, s2>>>();
    k_wrank1<<<NWc, 64, 0, s2>>>();
    cudaEventRecord(eMid, s2);        // keepF/inner/cnt all ready here
    k_featvec<<<Gv + Gs, 128, 0, s2>>>(feat, out, 0, Nh, Gv,
                                       off_keep, off_w0, off_w1,
                                       off_dl0, off_dl1, off_i0, off_i1);

    // branch B (captured stream): PE (no deps), then second half of feat+scalars
    k_pe4<<<(N + 3) / 4, 128>>>(coords, out, N, off_pe0, off_pe1);
    cudaStreamWaitEvent(0, eMid, 0);  // rank results ready before featvec B
    k_featvec<<<Gv + Gs, 128>>>(feat, out, Nh, N, Gv,
                                off_keep, off_w0, off_w1,
                                off_dl0, off_dl1, off_i0, off_i1);

    cudaEventRecord(eJoin, s2);
    cudaStreamWaitEvent(0, eJoin, 0); // join: stream 0 completes both branches
    // s2/events deliberately not destroyed: destroying capture-participating
    // resources invalidates the capture; kernel_launch runs only a few times.
}

// round 16
// speedup vs baseline: 1.1141x; 1.0022x over previous
#include <cuda_runtime.h>
#include <stdint.h>

// ---------------- problem constants ----------------
// SPARSE_SHAPE (468,468,1), WINDOW (12,12,1), BATCH 4
// _NX=_NY=40, _NZ=2 ; win_z==0 always ; full_win = 2*compact
// compact win id = b*1600 + wx*40 + wy  in [0, 6400)
#define NWc   6400
#define CAP   512               // max voxels per window (uniform data: ~49 mean)
#define MAXN  327680
#define FULLM 0xFFFFFFFFu
#define KLOG  0.4152410118609203f   // 4*log2(1e4)/128

// ---------------- static scratch (no allocations; zero-initialized) ---------
// g_cnt0/g_cnt1 are zero at load and restored to zero by the wrank kernels
// each replay (each block resets the counter it consumed).
__device__ int           g_cnt0[NWc];
__device__ int           g_cnt1[NWc];
__device__ int           g_bkt0[NWc * CAP];
__device__ int           g_bkt1[NWc * CAP];
__device__ int           g_winc0[MAXN];
__device__ int           g_winc1[MAXN];
__device__ int           g_inner0[MAXN];
__device__ int           g_inner1[MAXN];
__device__ signed char   g_dl0[MAXN];
__device__ signed char   g_dl1[MAXN];
__device__ unsigned char g_keep0[MAXN];
__device__ unsigned char g_keepF[MAXN];

__device__ __forceinline__ void lvl_target(int n, int& lvl, int& target) {
    if (n < 16)      { lvl = 0; target = 16; }
    else if (n < 32) { lvl = 1; target = 32; }
    else if (n < 64) { lvl = 2; target = 64; }
    else             { lvl = 3; target = 144; }
}

// ---------------- phase 1: window ids + bucket scatter (round 0) ------------
__global__ void k_scatter0(const int* __restrict__ coords, int N) {
    int i = blockIdx.x * blockDim.x + threadIdx.x;
    if (i < N) {
        int4 cc = ((const int4*)coords)[i];          // (b,z,y,x)
        int b = cc.x, y = cc.z, x = cc.w;
        int w0 = b * 1600 + ((x + 12) / 12) * 40 + ((y + 12) / 12);
        int w1 = b * 1600 + ((x + 6)  / 12) * 40 + ((y + 6)  / 12);
        g_winc0[i] = w0;
        g_winc1[i] = w1;
        int pos = atomicAdd(&g_cnt0[w0], 1);
        if (pos < CAP) g_bkt0[w0 * CAP + pos] = i;
    }
}

// ---------------- phase 2: rank round 0 + dl0 + scatter to round-1 buckets --
// rank = number of bucket entries with smaller voxel index (stable).
// Resets g_cnt0[w]=0 at the end (zero-invariant for next replay).
__global__ void __launch_bounds__(64)
k_wrank0s1() {
    __shared__ int s[CAP];
    int w = blockIdx.x;
    int n = g_cnt0[w];
    if (n > CAP) n = CAP;
    for (int t = threadIdx.x; t < n; t += 64) s[t] = g_bkt0[w * CAP + t];
    __syncthreads();
    int lvl, target; lvl_target(n, lvl, target);
    for (int e = threadIdx.x; e < n; e += 64) {
        int my = s[e];
        int r = 0;
        for (int j = 0; j < n; j++) r += (s[j] < my);
        g_inner0[my] = r;
        g_dl0[my] = (signed char)lvl;
        int kp = (r < target);
        g_keep0[my] = kp;
        if (kp) {
            int w1 = g_winc1[my];
            int pos = atomicAdd(&g_cnt1[w1], 1);
            if (pos < CAP) g_bkt1[w1 * CAP + pos] = my;
        } else {
            g_inner1[my] = -1;
            g_dl1[my]    = -1;
            g_keepF[my]  = 0;
        }
    }
    if (threadIdx.x == 0) g_cnt0[w] = 0;   // restore zero-invariant
}

// ---------------- phase 3: per-window stable rank (round 1) + dl1 -----------
__global__ void __launch_bounds__(64)
k_wrank1() {
    __shared__ int s[CAP];
    int w = blockIdx.x;
    int n = g_cnt1[w];
    if (n > CAP) n = CAP;
    for (int t = threadIdx.x; t < n; t += 64) s[t] = g_bkt1[w * CAP + t];
    __syncthreads();
    int lvl, target; lvl_target(n, lvl, target);
    for (int e = threadIdx.x; e < n; e += 64) {
        int my = s[e];
        int r = 0;
        for (int j = 0; j < n; j++) r += (s[j] < my);
        g_inner1[my] = r;
        g_dl1[my] = (signed char)lvl;
        g_keepF[my] = (r < target) ? 1 : 0;
    }
    if (threadIdx.x == 0) g_cnt1[w] = 0;   // restore zero-invariant
}

// ---------------- branch B: positional embeddings, SHORT blocks -------------
// One block = exactly 4 rows (warp per row), then exit. Short blocks recycle
// SM slots constantly so the concurrent aux chain co-schedules immediately.
__global__ void __launch_bounds__(128)
k_pe4(const int* __restrict__ coords, float* __restrict__ out, int N,
      size_t off_pe0, size_t off_pe1) {
    int warp = threadIdx.x >> 5, lane = threadIdx.x & 31;
    int i = blockIdx.x * 4 + warp;
    if (i >= N) return;
    int t = lane & 15;
    float rec0 = exp2f(-(float)(2 * t)     * KLOG);
    float rec1 = exp2f(-(float)(2 * t + 1) * KLOG);

    int x = __ldg(&coords[i * 4 + 3]);
    int y = __ldg(&coords[i * 4 + 2]);
    int v = (lane < 16) ? x : y;
    float v0 = (float)(v % 12) - 6.0f;
    float v1 = (float)((v + 6) % 12) - 6.0f;

    float4 p0, p1; float a;
    a = v0 * rec0; p0.x = __sinf(a); p0.y = __cosf(a);
    a = v0 * rec1; p0.z = __sinf(a); p0.w = __cosf(a);
    a = v1 * rec0; p1.x = __sinf(a); p1.y = __cosf(a);
    a = v1 * rec1; p1.z = __sinf(a); p1.w = __cosf(a);

    size_t row4 = (size_t)i * 32 + lane;
    ((float4*)(out + off_pe0))[row4] = p0;
    ((float4*)(out + off_pe1))[row4] = p1;
}

// ---------------- final: feat mask (vector) + scalar vectors, block-split ---
// Blocks [0,Gv): warp-per-row float4 feat masking (grid-stride).
// Blocks [Gv,..): flat one-thread-per-voxel scalar outputs — now pure flat
// reads (dl0/dl1 precomputed), no dependent gathers.
__global__ void __launch_bounds__(128)
k_featvec(const float* __restrict__ feat, float* __restrict__ out, int N, int Gv,
          size_t off_keep, size_t off_w0, size_t off_w1,
          size_t off_dl0, size_t off_dl1, size_t off_i0, size_t off_i1) {
    if (blockIdx.x < (unsigned)Gv) {
        int warp = threadIdx.x >> 5, lane = threadIdx.x & 31;
        for (int i = blockIdx.x * 4 + warp; i < N; i += Gv * 4) {
            float kf = g_keepF[i] ? 1.0f : 0.0f;
            size_t row4 = (size_t)i * 32 + lane;
            float4 f = ((const float4*)feat)[row4];
            f.x *= kf; f.y *= kf; f.z *= kf; f.w *= kf;
            ((float4*)out)[row4] = f;
        }
    } else {
        int nb = gridDim.x - Gv;
        for (int i = (blockIdx.x - Gv) * 128 + threadIdx.x; i < N; i += nb * 128) {
            out[off_keep + i] = g_keepF[i] ? 1.0f : 0.0f;
            out[off_w0 + i]   = (float)(2 * g_winc0[i]);
            out[off_w1 + i]   = (float)(2 * g_winc1[i]);
            out[off_dl0 + i]  = (float)g_dl0[i];
            out[off_dl1 + i]  = (float)g_dl1[i];
            out[off_i0 + i]   = (float)g_inner0[i];
            out[off_i1 + i]   = (float)g_inner1[i];
        }
    }
}

// ---------------- launch ----------------
extern "C" void kernel_launch(void* const* d_in, const int* in_sizes, int n_in,
                              void* d_out, int out_size) {
    const float* feat   = (const float*)d_in[0];
    const int*   coords = (const int*)d_in[1];
    int N = in_sizes[1] / 4;
    int C = in_sizes[0] / N;          // 128 (layout constants assume this)
    if (N > MAXN) N = MAXN;

    float* out = (float*)d_out;
    size_t Ns = (size_t)N, Cs = (size_t)C;
    size_t off = Ns * Cs;             // feat at 0
    size_t off_keep = off; off += Ns;
    size_t off_w0   = off; off += Ns;
    size_t off_w1   = off; off += Ns;
    size_t off_dl0  = off; off += Ns;
    size_t off_dl1  = off; off += Ns;
    size_t off_i0   = off; off += Ns;
    size_t off_i1   = off; off += Ns;
    size_t off_pe0  = off; off += Ns * Cs;
    size_t off_pe1  = off;

    // R12 structure (best known): aux chain on HIGH-priority s2; short-block
    // PE on the captured stream; join at the end.
    int prLow = 0, prHigh = 0;
    cudaDeviceGetStreamPriorityRange(&prLow, &prHigh);
    cudaStream_t s2;
    cudaStreamCreateWithPriority(&s2, cudaStreamNonBlocking, prHigh);
    cudaEvent_t eFork, eJoin;
    cudaEventCreateWithFlags(&eFork, cudaEventDisableTiming);
    cudaEventCreateWithFlags(&eJoin, cudaEventDisableTiming);

    cudaEventRecord(eFork, 0);
    cudaStreamWaitEvent(s2, eFork, 0);

    // branch A (s2, high prio): rank chain + all keep-dependent outputs
    k_scatter0<<<(N + 255) / 256, 256, 0, s2>>>(coords, N);
    k_wrank0s1<<<NWc, 64, 0, s2>>>();
    k_wrank1<<<NWc, 64, 0, s2>>>();
    int Gv = 1184;                    // vector blocks; + 592 scalar blocks
    k_featvec<<<Gv + 592, 128, 0, s2>>>(feat, out, N, Gv,
                                        off_keep, off_w0, off_w1,
                                        off_dl0, off_dl1, off_i0, off_i1);

    // branch B (captured stream): PE, short blocks (coords-only)
    k_pe4<<<(N + 3) / 4, 128>>>(coords, out, N, off_pe0, off_pe1);

    cudaEventRecord(eJoin, s2);
    cudaStreamWaitEvent(0, eJoin, 0);   // join
    // s2/events deliberately not destroyed: destroying capture-participating
    // resources invalidates the capture; kernel_launch runs only a few times.
}